// round 10
// baseline (speedup 1.0000x reference)
#include <cuda_runtime.h>
#include <cuda_fp16.h>
#include <math.h>
#include <cstdint>

#define BATCH 2048
#define SEQ   200
#define HDIM  512
#define MTOT  (BATCH * SEQ)   // 409600
#define NPLANES 4             // 4 o-tiles of 128 cols

// ---------------- static device scratch (no allocation) ----------------
__device__ float  g_l[BATCH * HDIM];          // Wr(last_memory)  [B,512]
__device__ float  g_spart[NPLANES][MTOT];     // partial scores
__device__ __half g_Wh[HDIM * HDIM];          // Ur_w fp16
__device__ __half g_Ah[(size_t)MTOT * HDIM];  // all_memory fp16 (written by score)

// ======================= helpers =======================
__device__ __forceinline__ uint32_t smem_u32(const void* p) {
    uint32_t a;
    asm("{ .reg .u64 t; cvta.to.shared.u64 t, %1; cvt.u32.u64 %0, t; }"
        : "=r"(a) : "l"(p));
    return a;
}
#define SWZ(off) ((off) ^ (((off) >> 3) & 0x70))

#define LDSM_X4(r, a) \
    asm volatile("ldmatrix.sync.aligned.m8n8.x4.shared.b16 {%0,%1,%2,%3}, [%4];" \
        : "=r"((r)[0]), "=r"((r)[1]), "=r"((r)[2]), "=r"((r)[3]) : "r"(a))
#define LDSM_X2(r, a) \
    asm volatile("ldmatrix.sync.aligned.m8n8.x2.shared.b16 {%0,%1}, [%2];" \
        : "=r"((r)[0]), "=r"((r)[1]) : "r"(a))
#define MMA_F16(d, a, b) \
    asm volatile("mma.sync.aligned.m16n8k16.row.col.f32.f16.f16.f32 " \
        "{%0,%1,%2,%3},{%4,%5,%6,%7},{%8,%9},{%0,%1,%2,%3};" \
        : "+f"((d)[0]), "+f"((d)[1]), "+f"((d)[2]), "+f"((d)[3]) \
        : "r"((a)[0]), "r"((a)[1]), "r"((a)[2]), "r"((a)[3]), \
          "r"((b)[0]), "r"((b)[1]))
#define CPASYNC16(dst, src) \
    asm volatile("cp.async.cg.shared.global [%0], [%1], 16;" \
        :: "r"(dst), "l"(src) : "memory")
#define CPASYNC_COMMIT() asm volatile("cp.async.commit_group;" ::: "memory")
#define CPASYNC_WAITG(n) asm volatile("cp.async.wait_group %0;" :: "n"(n) : "memory")
#define STS128(addr, a, b, c, d) \
    asm volatile("st.shared.v4.b32 [%0], {%1, %2, %3, %4};" \
        :: "r"(addr), "r"(a), "r"(b), "r"(c), "r"(d) : "memory")

__device__ __forceinline__ float fast_tanh(float x) {
    float e = __expf(2.0f * x);
    return 1.0f - __fdividef(2.0f, e + 1.0f);
}

// =============================================================================
// W convert kernel: Ur_w fp32 -> fp16 (tiny, 512KB)
// =============================================================================
__global__ void __launch_bounds__(256)
whalf_kernel(const float* __restrict__ Ur)
{
    int i = blockIdx.x * 256 + threadIdx.x;       // float4 units, 65536
    float4 v = reinterpret_cast<const float4*>(Ur)[i];
    __half2 h0 = __float22half2_rn(make_float2(v.x, v.y));
    __half2 h1 = __float22half2_rn(make_float2(v.z, v.w));
    reinterpret_cast<__half2*>(g_Wh)[2 * i + 0] = h0;
    reinterpret_cast<__half2*>(g_Wh)[2 * i + 1] = h1;
}

// =============================================================================
// K1: l = last_memory @ Wr^T  (SIMT fp32, ~52us)
// =============================================================================
__global__ void __launch_bounds__(256)
gemm_l_kernel(const float* __restrict__ A, const float* __restrict__ W)
{
    const int tid = threadIdx.x;
    const int tx  = tid & 15;
    const int ty  = tid >> 4;
    const int m0  = blockIdx.x * 64;
    const int o0  = blockIdx.y * 128;

    __shared__ float As[64][33];
    __shared__ float Ws[128][33];

    float acc[4][8];
#pragma unroll
    for (int i = 0; i < 4; i++)
#pragma unroll
        for (int j = 0; j < 8; j++) acc[i][j] = 0.0f;

    for (int k0 = 0; k0 < HDIM; k0 += 32) {
#pragma unroll
        for (int t = 0; t < 2; t++) {
            int f = t * 256 + tid, r = f >> 3, c4 = (f & 7) << 2;
            float4 v = *reinterpret_cast<const float4*>(&A[(size_t)(m0 + r) * HDIM + k0 + c4]);
            As[r][c4] = v.x; As[r][c4 + 1] = v.y; As[r][c4 + 2] = v.z; As[r][c4 + 3] = v.w;
        }
#pragma unroll
        for (int t = 0; t < 4; t++) {
            int f = t * 256 + tid, r = f >> 3, c4 = (f & 7) << 2;
            float4 v = *reinterpret_cast<const float4*>(&W[(size_t)(o0 + r) * HDIM + k0 + c4]);
            Ws[r][c4] = v.x; Ws[r][c4 + 1] = v.y; Ws[r][c4 + 2] = v.z; Ws[r][c4 + 3] = v.w;
        }
        __syncthreads();
#pragma unroll
        for (int kk = 0; kk < 32; kk++) {
            float a[4], w[8];
#pragma unroll
            for (int i = 0; i < 4; i++) a[i] = As[ty * 4 + i][kk];
#pragma unroll
            for (int j = 0; j < 8; j++) w[j] = Ws[tx + 16 * j][kk];
#pragma unroll
            for (int i = 0; i < 4; i++)
#pragma unroll
                for (int j = 0; j < 8; j++) acc[i][j] += a[i] * w[j];
        }
        __syncthreads();
    }
#pragma unroll
    for (int i = 0; i < 4; i++) {
        int m = m0 + ty * 4 + i;
#pragma unroll
        for (int j = 0; j < 8; j++)
            g_l[(size_t)m * HDIM + o0 + tx + 16 * j] = acc[i][j];
    }
}

// =============================================================================
// K2: fused convert + fp16 HMMA GEMM over ALL 4 o-planes per CTA.
// CTA = 128 m-rows. A fp32 loaded/converted once (plane 0), cached as fp16
// in smem (8 chunk-tiles, 128KB) and written to g_Ah for finish_kernel.
// B streamed via 2-stage cp.async (16KB stages). 1 CTA/SM, regs uncapped.
// =============================================================================
#define OFF_VRE   0
#define OFF_PART  2048
#define OFF_A     4096
#define A_CH      16384           // one 128x64 fp16 chunk tile
#define OFF_B     (OFF_A + 8 * A_CH)          // 135168
#define B_STG     16384
#define SMEM_TOTAL (OFF_B + 2 * B_STG)        // 167936

__global__ void __launch_bounds__(256, 1)
score_kernel(const float* __restrict__ A,       // all_memory fp32 [M,512]
             const float* __restrict__ vre)     // [512]
{
    extern __shared__ char smem[];
    const uint32_t sb  = smem_u32(smem);
    const int tid = threadIdx.x;
    const int wid = tid >> 5;
    const int lid = tid & 31;
    const int wm  = wid >> 2;     // 0..1
    const int wn  = wid & 3;      // 0..3
    const int m0  = blockIdx.x * 128;

    float* svre = reinterpret_cast<float*>(smem + OFF_VRE);
    svre[tid] = vre[tid];
    svre[tid + 256] = vre[tid + 256];

    // producer roles
    const int ar = tid >> 1;                  // row 0..127
    const int ah = (tid & 1);                 // k half (32 elements)
    const float*  Abase  = A    + (size_t)(m0 + ar) * HDIM + ah * 32;
    __half*       AhOut  = g_Ah + (size_t)(m0 + ar) * HDIM + ah * 32;
    const __half* Bbase  = g_Wh + (size_t)ar * HDIM + ah * 32;  // + plane*128 rows
    const uint32_t roff  = (uint32_t)(ar * 128 + ah * 64);

    float acc[4][4][4];
#pragma unroll
    for (int i = 0; i < 4; i++)
#pragma unroll
        for (int j = 0; j < 4; j++)
#pragma unroll
            for (int q = 0; q < 4; q++) acc[i][j][q] = 0.0f;

    // ---- prologue: B chunks 0,1 + A fp32 chunk 0 ----
#pragma unroll
    for (int p = 0; p < 2; p++) {
        const uint32_t st = sb + OFF_B + p * B_STG;
#pragma unroll
        for (int q = 0; q < 4; q++)
            CPASYNC16(st + SWZ(roff + q * 16), Bbase + p * 64 + q * 8);
        CPASYNC_COMMIT();
    }
    float4 va[8];
#pragma unroll
    for (int q = 0; q < 8; q++)
        va[q] = *reinterpret_cast<const float4*>(Abase + q * 4);

#pragma unroll 1
    for (int t = 0; t < 32; ++t) {
        const int pl = t >> 3, c = t & 7;

        // issue next B chunk
        if (t < 31) {
            const int tn = t + 1;
            const __half* src = Bbase + (size_t)(tn >> 3) * 128 * HDIM + (tn & 7) * 64;
            const uint32_t stn = sb + OFF_B + ((t + 1) & 1) * B_STG;
#pragma unroll
            for (int q = 0; q < 4; q++)
                CPASYNC16(stn + SWZ(roff + q * 16), src + q * 8);
            CPASYNC_COMMIT();
            CPASYNC_WAITG(1);
        } else {
            CPASYNC_WAITG(0);
        }

        // plane 0: convert A chunk c into smem + g_Ah, prefetch chunk c+1
        if (pl == 0) {
            uint32_t h[16];
#pragma unroll
            for (int g = 0; g < 4; g++) {
                float4 u = va[2 * g], v = va[2 * g + 1];
                __half2 h0 = __float22half2_rn(make_float2(u.x, u.y));
                __half2 h1 = __float22half2_rn(make_float2(u.z, u.w));
                __half2 h2 = __float22half2_rn(make_float2(v.x, v.y));
                __half2 h3 = __float22half2_rn(make_float2(v.z, v.w));
                h[4 * g + 0] = reinterpret_cast<uint32_t&>(h0);
                h[4 * g + 1] = reinterpret_cast<uint32_t&>(h1);
                h[4 * g + 2] = reinterpret_cast<uint32_t&>(h2);
                h[4 * g + 3] = reinterpret_cast<uint32_t&>(h3);
                STS128(sb + OFF_A + c * A_CH + SWZ(roff + g * 16),
                       h[4 * g], h[4 * g + 1], h[4 * g + 2], h[4 * g + 3]);
            }
#pragma unroll
            for (int g = 0; g < 4; g++) {
                uint4 o;
                o.x = h[4 * g]; o.y = h[4 * g + 1]; o.z = h[4 * g + 2]; o.w = h[4 * g + 3];
                reinterpret_cast<uint4*>(AhOut + c * 64)[g] = o;
            }
            if (c < 7) {
#pragma unroll
                for (int q = 0; q < 8; q++)
                    va[q] = *reinterpret_cast<const float4*>(Abase + (c + 1) * 64 + q * 4);
            }
        }
        __syncthreads();

        // ---- MMAs: A chunk c (smem-resident) x B stage t&1 ----
        const uint32_t stA = sb + OFF_A + c * A_CH;
        const uint32_t stB = sb + OFF_B + (t & 1) * B_STG;
#pragma unroll
        for (int ks = 0; ks < 4; ks++) {
            uint32_t bf[4][2];
#pragma unroll
            for (int nf = 0; nf < 4; nf++) {
                uint32_t row = wn * 32 + nf * 8 + (lid & 7);
                uint32_t kb  = ks * 32 + ((lid >> 3) & 1) * 16;
                LDSM_X2(bf[nf], stB + SWZ(row * 128 + kb));
            }
#pragma unroll
            for (int mf = 0; mf < 4; mf++) {
                uint32_t row = wm * 64 + mf * 16 + (lid & 15);
                uint32_t kb  = ks * 32 + (lid >> 4) * 16;
                uint32_t af[4];
                LDSM_X4(af, stA + SWZ(row * 128 + kb));
#pragma unroll
                for (int nf = 0; nf < 4; nf++)
                    MMA_F16(acc[mf][nf], af, bf[nf]);
            }
        }

        // ---- end of plane: fused epilogue, reset acc ----
        if (c == 7) {
            float* part = reinterpret_cast<float*>(smem + OFF_PART);
            const int o0 = pl * 128;
            const int r0 = lid >> 2;
            const int cb = 2 * (lid & 3);
#pragma unroll
            for (int mf = 0; mf < 4; mf++) {
                int R0 = wm * 64 + mf * 16 + r0;
                int R1 = R0 + 8;
                const float* lA = g_l + (size_t)((m0 + R0) / SEQ) * HDIM + o0;
                const float* lB = g_l + (size_t)((m0 + R1) / SEQ) * HDIM + o0;
                float p0 = 0.0f, p1 = 0.0f;
#pragma unroll
                for (int nf = 0; nf < 4; nf++) {
                    int cl = wn * 32 + nf * 8 + cb;
                    p0 += fast_tanh(acc[mf][nf][0] + lA[cl])     * svre[o0 + cl];
                    p0 += fast_tanh(acc[mf][nf][1] + lA[cl + 1]) * svre[o0 + cl + 1];
                    p1 += fast_tanh(acc[mf][nf][2] + lB[cl])     * svre[o0 + cl];
                    p1 += fast_tanh(acc[mf][nf][3] + lB[cl + 1]) * svre[o0 + cl + 1];
#pragma unroll
                    for (int q = 0; q < 4; q++) acc[mf][nf][q] = 0.0f;
                }
                p0 += __shfl_xor_sync(0xffffffffu, p0, 1);
                p0 += __shfl_xor_sync(0xffffffffu, p0, 2);
                p1 += __shfl_xor_sync(0xffffffffu, p1, 1);
                p1 += __shfl_xor_sync(0xffffffffu, p1, 2);
                if ((lid & 3) == 0) {
                    part[R0 * 4 + wn] = p0;
                    part[R1 * 4 + wn] = p1;
                }
            }
            __syncthreads();
            if (tid < 128) {
                float s = part[tid * 4 + 0] + part[tid * 4 + 1]
                        + part[tid * 4 + 2] + part[tid * 4 + 3];
                g_spart[pl][m0 + tid] = s;
            }
            __syncthreads();
        }
    }
}

// =============================================================================
// K3: per-batch softmax over S, context (fp16 g_Ah), 2-class head
// =============================================================================
__device__ __forceinline__ float block_reduce_max(float v, float* red, int tid) {
    red[tid] = v; __syncthreads();
#pragma unroll
    for (int off = 128; off > 0; off >>= 1) {
        if (tid < off) red[tid] = fmaxf(red[tid], red[tid + off]);
        __syncthreads();
    }
    float r = red[0]; __syncthreads(); return r;
}
__device__ __forceinline__ float block_reduce_sum(float v, float* red, int tid) {
    red[tid] = v; __syncthreads();
#pragma unroll
    for (int off = 128; off > 0; off >>= 1) {
        if (tid < off) red[tid] = red[tid] + red[tid + off];
        __syncthreads();
    }
    float r = red[0]; __syncthreads(); return r;
}

__global__ void __launch_bounds__(256)
finish_kernel(const float* __restrict__ wre,
              float* __restrict__ out)
{
    const int b = blockIdx.x, tid = threadIdx.x;
    __shared__ float attn[SEQ];
    __shared__ float red[256];

    float sc = -INFINITY;
    if (tid < SEQ) {
        float s = 0.0f;
#pragma unroll
        for (int p = 0; p < NPLANES; p++) s += g_spart[p][(size_t)b * SEQ + tid];
        sc = s;
    }
    float mx = block_reduce_max(sc, red, tid);
    float e = (tid < SEQ) ? expf(sc - mx) : 0.0f;
    float denom = block_reduce_sum(e, red, tid);
    if (tid < SEQ) attn[tid] = e / denom;
    __syncthreads();

    const __half* am = g_Ah + (size_t)b * SEQ * HDIM;
    float c0a = 0.0f, c1a = 0.0f, c0b = 0.0f, c1b = 0.0f;
#pragma unroll 2
    for (int s = 0; s < SEQ; s += 2) {
        float w0 = attn[s];
        float w1 = attn[s + 1];
        __half2 ha = *reinterpret_cast<const __half2*>(am + (size_t)s * HDIM + 2 * tid);
        __half2 hb = *reinterpret_cast<const __half2*>(am + (size_t)(s + 1) * HDIM + 2 * tid);
        float2 fa = __half22float2(ha);
        float2 fb = __half22float2(hb);
        c0a = fmaf(w0, fa.x, c0a);
        c1a = fmaf(w0, fa.y, c1a);
        c0b = fmaf(w1, fb.x, c0b);
        c1b = fmaf(w1, fb.y, c1b);
    }
    float c0 = c0a + c0b, c1 = c1a + c1b;
    float p0 = c0 * wre[2 * tid]        + c1 * wre[2 * tid + 1];
    float p1 = c0 * wre[HDIM + 2 * tid] + c1 * wre[HDIM + 2 * tid + 1];
    float L0 = block_reduce_sum(p0, red, tid);
    float L1 = block_reduce_sum(p1, red, tid);
    if (tid == 0) {
        float m  = fmaxf(L0, L1);
        float e0 = expf(L0 - m), e1 = expf(L1 - m);
        float inv = 1.0f / (e0 + e1);
        out[(size_t)b * 2 + 0] = e0 * inv;
        out[(size_t)b * 2 + 1] = e1 * inv;
    }
}

// =============================================================================
// launch
// =============================================================================
extern "C" void kernel_launch(void* const* d_in, const int* in_sizes, int n_in,
                              void* d_out, int out_size)
{
    const float* all_memory  = (const float*)d_in[0];
    const float* last_memory = (const float*)d_in[1];
    const float* Ur_w        = (const float*)d_in[2];
    const float* Wr_w        = (const float*)d_in[3];
    const float* Vre_w       = (const float*)d_in[4];
    const float* Wre_w       = (const float*)d_in[5];
    float* out = (float*)d_out;

    cudaFuncSetAttribute(score_kernel,
                         cudaFuncAttributeMaxDynamicSharedMemorySize, SMEM_TOTAL);

    whalf_kernel<<<256, 256>>>(Ur_w);
    gemm_l_kernel<<<dim3(BATCH / 64, HDIM / 128), 256>>>(last_memory, Wr_w);
    score_kernel<<<MTOT / 128, 256, SMEM_TOTAL>>>(all_memory, Vre_w);
    finish_kernel<<<BATCH, 256>>>(Wre_w, out);
}

// round 11
// speedup vs baseline: 1.1240x; 1.1240x over previous
#include <cuda_runtime.h>
#include <cuda_fp16.h>
#include <math.h>
#include <cstdint>

#define BATCH 2048
#define SEQ   200
#define HDIM  512
#define MTOT  (BATCH * SEQ)   // 409600
#define NPLANES 4             // 4 o-tiles of 128 cols

// ---------------- static device scratch (no allocation) ----------------
__device__ float  g_l[BATCH * HDIM];          // Wr(last_memory)  [B,512]
__device__ float  g_spart[NPLANES][MTOT];     // partial scores
__device__ __half g_Wh[HDIM * HDIM];          // Ur_w fp16
__device__ __half g_Ah[(size_t)MTOT * HDIM];  // all_memory fp16 (written by score)

// ======================= helpers =======================
__device__ __forceinline__ uint32_t smem_u32(const void* p) {
    uint32_t a;
    asm("{ .reg .u64 t; cvta.to.shared.u64 t, %1; cvt.u32.u64 %0, t; }"
        : "=r"(a) : "l"(p));
    return a;
}
// 64-byte-row swizzle (Swizzle<2,4,3>): conflict-free ldmatrix on 64B rows
#define SWZ64(off) ((off) ^ (((off) >> 3) & 0x30))

#define LDSM_X4(r, a) \
    asm volatile("ldmatrix.sync.aligned.m8n8.x4.shared.b16 {%0,%1,%2,%3}, [%4];" \
        : "=r"((r)[0]), "=r"((r)[1]), "=r"((r)[2]), "=r"((r)[3]) : "r"(a))
#define LDSM_X2(r, a) \
    asm volatile("ldmatrix.sync.aligned.m8n8.x2.shared.b16 {%0,%1}, [%2];" \
        : "=r"((r)[0]), "=r"((r)[1]) : "r"(a))
#define MMA_F16(d, a, b) \
    asm volatile("mma.sync.aligned.m16n8k16.row.col.f32.f16.f16.f32 " \
        "{%0,%1,%2,%3},{%4,%5,%6,%7},{%8,%9},{%0,%1,%2,%3};" \
        : "+f"((d)[0]), "+f"((d)[1]), "+f"((d)[2]), "+f"((d)[3]) \
        : "r"((a)[0]), "r"((a)[1]), "r"((a)[2]), "r"((a)[3]), \
          "r"((b)[0]), "r"((b)[1]))
#define CPASYNC16(dst, src) \
    asm volatile("cp.async.cg.shared.global [%0], [%1], 16;" \
        :: "r"(dst), "l"(src) : "memory")
#define CPASYNC_COMMIT() asm volatile("cp.async.commit_group;" ::: "memory")
#define CPASYNC_WAITG(n) asm volatile("cp.async.wait_group %0;" :: "n"(n) : "memory")
#define STS128(addr, a, b, c, d) \
    asm volatile("st.shared.v4.b32 [%0], {%1, %2, %3, %4};" \
        :: "r"(addr), "r"(a), "r"(b), "r"(c), "r"(d) : "memory")

__device__ __forceinline__ float fast_tanh(float x) {
    float e = __expf(2.0f * x);
    return 1.0f - __fdividef(2.0f, e + 1.0f);
}

// =============================================================================
// W convert kernel: Ur_w fp32 -> fp16 (tiny, ~5us)
// =============================================================================
__global__ void __launch_bounds__(256)
whalf_kernel(const float* __restrict__ Ur)
{
    int i = blockIdx.x * 256 + threadIdx.x;       // float4 units, 65536
    float4 v = reinterpret_cast<const float4*>(Ur)[i];
    __half2 h0 = __float22half2_rn(make_float2(v.x, v.y));
    __half2 h1 = __float22half2_rn(make_float2(v.z, v.w));
    reinterpret_cast<__half2*>(g_Wh)[2 * i + 0] = h0;
    reinterpret_cast<__half2*>(g_Wh)[2 * i + 1] = h1;
}

// =============================================================================
// K1: l = last_memory @ Wr^T  (SIMT fp32, ~52us)
// =============================================================================
__global__ void __launch_bounds__(256)
gemm_l_kernel(const float* __restrict__ A, const float* __restrict__ W)
{
    const int tid = threadIdx.x;
    const int tx  = tid & 15;
    const int ty  = tid >> 4;
    const int m0  = blockIdx.x * 64;
    const int o0  = blockIdx.y * 128;

    __shared__ float As[64][33];
    __shared__ float Ws[128][33];

    float acc[4][8];
#pragma unroll
    for (int i = 0; i < 4; i++)
#pragma unroll
        for (int j = 0; j < 8; j++) acc[i][j] = 0.0f;

    for (int k0 = 0; k0 < HDIM; k0 += 32) {
#pragma unroll
        for (int t = 0; t < 2; t++) {
            int f = t * 256 + tid, r = f >> 3, c4 = (f & 7) << 2;
            float4 v = *reinterpret_cast<const float4*>(&A[(size_t)(m0 + r) * HDIM + k0 + c4]);
            As[r][c4] = v.x; As[r][c4 + 1] = v.y; As[r][c4 + 2] = v.z; As[r][c4 + 3] = v.w;
        }
#pragma unroll
        for (int t = 0; t < 4; t++) {
            int f = t * 256 + tid, r = f >> 3, c4 = (f & 7) << 2;
            float4 v = *reinterpret_cast<const float4*>(&W[(size_t)(o0 + r) * HDIM + k0 + c4]);
            Ws[r][c4] = v.x; Ws[r][c4 + 1] = v.y; Ws[r][c4 + 2] = v.z; Ws[r][c4 + 3] = v.w;
        }
        __syncthreads();
#pragma unroll
        for (int kk = 0; kk < 32; kk++) {
            float a[4], w[8];
#pragma unroll
            for (int i = 0; i < 4; i++) a[i] = As[ty * 4 + i][kk];
#pragma unroll
            for (int j = 0; j < 8; j++) w[j] = Ws[tx + 16 * j][kk];
#pragma unroll
            for (int i = 0; i < 4; i++)
#pragma unroll
                for (int j = 0; j < 8; j++) acc[i][j] += a[i] * w[j];
        }
        __syncthreads();
    }
#pragma unroll
    for (int i = 0; i < 4; i++) {
        int m = m0 + ty * 4 + i;
#pragma unroll
        for (int j = 0; j < 8; j++)
            g_l[(size_t)m * HDIM + o0 + tx + 16 * j] = acc[i][j];
    }
}

// =============================================================================
// K2: fused convert + fp16 HMMA over ALL 4 o-planes, 64 m-rows per CTA.
// A fp32 read once (plane 0, converted one chunk ahead), cached fp16 in smem
// (16 half-chunk tiles of 64x32, 64KB total) + written to g_Ah.
// B: K=32 half-chunks, 3-stage cp.async pipeline (R9-proven ordering).
// smem ~92KB -> 2 CTAs/SM. Warps 2(m) x 4(n); per-warp 32m x 32n.
// =============================================================================
#define OFF_VRE   0                       // 512 floats
#define OFF_PART  2048                    // 64*4 floats
#define OFF_A     4096
#define A_HC      4096                    // 64 rows x 32k fp16
#define OFF_B     (OFF_A + 16 * A_HC)     // 69632
#define B_STG     8192                    // 128 rows x 32k fp16
#define SMEM_TOTAL (OFF_B + 3 * B_STG)    // 94208

__global__ void __launch_bounds__(256, 2)
score_kernel(const float* __restrict__ A,       // all_memory fp32 [M,512]
             const float* __restrict__ vre)     // [512]
{
    extern __shared__ char smem[];
    const uint32_t sb  = smem_u32(smem);
    const int tid = threadIdx.x;
    const int wid = tid >> 5;
    const int lid = tid & 31;
    const int wm  = wid >> 2;     // 0..1
    const int wn  = wid & 3;      // 0..3
    const int m0  = blockIdx.x * 64;

    float* svre = reinterpret_cast<float*>(smem + OFF_VRE);
    svre[tid] = vre[tid];
    svre[tid + 256] = vre[tid + 256];

    // A producer: thread -> (row ar, 8-float quarter aq)
    const int ar = tid >> 2;                  // 0..63
    const int aq = tid & 3;                   // 0..3
    const float* Abase = A    + (size_t)(m0 + ar) * HDIM + aq * 8;
    __half*      AhOut = g_Ah + (size_t)(m0 + ar) * HDIM + aq * 8;
    const uint32_t aoff = (uint32_t)(ar * 64 + aq * 16);

    // B producer: thread -> (row br, 16-half half bh); 2 x cp.async 16B
    const int br = tid >> 1;                  // 0..127
    const int bh = tid & 1;
    const uint32_t boff = (uint32_t)(br * 64 + bh * 32);

    float acc[2][4][4];
#pragma unroll
    for (int i = 0; i < 2; i++)
#pragma unroll
        for (int j = 0; j < 4; j++)
#pragma unroll
            for (int q = 0; q < 4; q++) acc[i][j][q] = 0.0f;

    // ---- prologue: B half-chunks 0,1 into stages 0,1 ----
#pragma unroll
    for (int p = 0; p < 2; p++) {
        const __half* src = g_Wh + (size_t)br * HDIM + p * 32 + bh * 16;
        const uint32_t st = sb + OFF_B + p * B_STG;
        CPASYNC16(st + SWZ64(boff),      src);
        CPASYNC16(st + SWZ64(boff + 16), src + 8);
        CPASYNC_COMMIT();
    }
    // A: convert half-chunk 0, prefetch half-chunk 1
    float4 va0, va1;
    va0 = *reinterpret_cast<const float4*>(Abase);
    va1 = *reinterpret_cast<const float4*>(Abase + 4);
    {
        __half2 h0 = __float22half2_rn(make_float2(va0.x, va0.y));
        __half2 h1 = __float22half2_rn(make_float2(va0.z, va0.w));
        __half2 h2 = __float22half2_rn(make_float2(va1.x, va1.y));
        __half2 h3 = __float22half2_rn(make_float2(va1.z, va1.w));
        STS128(sb + OFF_A + SWZ64(aoff),
               reinterpret_cast<uint32_t&>(h0), reinterpret_cast<uint32_t&>(h1),
               reinterpret_cast<uint32_t&>(h2), reinterpret_cast<uint32_t&>(h3));
        uint4 o;
        o.x = reinterpret_cast<uint32_t&>(h0); o.y = reinterpret_cast<uint32_t&>(h1);
        o.z = reinterpret_cast<uint32_t&>(h2); o.w = reinterpret_cast<uint32_t&>(h3);
        *reinterpret_cast<uint4*>(AhOut) = o;
    }
    va0 = *reinterpret_cast<const float4*>(Abase + 32);
    va1 = *reinterpret_cast<const float4*>(Abase + 36);

#pragma unroll 1
    for (int t = 0; t < 64; ++t) {
        const int pl = t >> 4, c = t & 15;

        if (t < 63) { CPASYNC_WAITG(1); } else { CPASYNC_WAITG(0); }
        __syncthreads();

        // fill B half-chunk t+2 into stage (t+2)%3 (safe: last read at t-1)
        if (t + 2 < 64) {
            const int bi = t + 2;
            const __half* src = g_Wh + (size_t)((bi >> 4) * 128 + br) * HDIM
                              + (bi & 15) * 32 + bh * 16;
            const uint32_t stn = sb + OFF_B + ((t + 2) % 3) * B_STG;
            CPASYNC16(stn + SWZ64(boff),      src);
            CPASYNC16(stn + SWZ64(boff + 16), src + 8);
            CPASYNC_COMMIT();
        }

        // plane 0: convert A half-chunk c+1 (used next iteration), prefetch c+2
        if (pl == 0 && c < 15) {
            __half2 h0 = __float22half2_rn(make_float2(va0.x, va0.y));
            __half2 h1 = __float22half2_rn(make_float2(va0.z, va0.w));
            __half2 h2 = __float22half2_rn(make_float2(va1.x, va1.y));
            __half2 h3 = __float22half2_rn(make_float2(va1.z, va1.w));
            STS128(sb + OFF_A + (c + 1) * A_HC + SWZ64(aoff),
                   reinterpret_cast<uint32_t&>(h0), reinterpret_cast<uint32_t&>(h1),
                   reinterpret_cast<uint32_t&>(h2), reinterpret_cast<uint32_t&>(h3));
            uint4 o;
            o.x = reinterpret_cast<uint32_t&>(h0); o.y = reinterpret_cast<uint32_t&>(h1);
            o.z = reinterpret_cast<uint32_t&>(h2); o.w = reinterpret_cast<uint32_t&>(h3);
            *reinterpret_cast<uint4*>(AhOut + (c + 1) * 32) = o;
            if (c < 14) {
                va0 = *reinterpret_cast<const float4*>(Abase + (c + 2) * 32);
                va1 = *reinterpret_cast<const float4*>(Abase + (c + 2) * 32 + 4);
            }
        }

        // ---- MMAs: A half-chunk c (smem) x B stage t%3 ----
        const uint32_t stA = sb + OFF_A + c * A_HC;
        const uint32_t stB = sb + OFF_B + (t % 3) * B_STG;
#pragma unroll
        for (int ks = 0; ks < 2; ks++) {
            uint32_t bf[4][2];
#pragma unroll
            for (int nf = 0; nf < 4; nf++) {
                uint32_t row = wn * 32 + nf * 8 + (lid & 7);
                uint32_t kb  = ks * 32 + ((lid >> 3) & 1) * 16;
                LDSM_X2(bf[nf], stB + SWZ64(row * 64 + kb));
            }
#pragma unroll
            for (int mf = 0; mf < 2; mf++) {
                uint32_t row = wm * 32 + mf * 16 + (lid & 15);
                uint32_t kb  = ks * 32 + (lid >> 4) * 16;
                uint32_t af[4];
                LDSM_X4(af, stA + SWZ64(row * 64 + kb));
#pragma unroll
                for (int nf = 0; nf < 4; nf++)
                    MMA_F16(acc[mf][nf], af, bf[nf]);
            }
        }

        // ---- end of plane: fused epilogue, reset acc ----
        if (c == 15) {
            float* part = reinterpret_cast<float*>(smem + OFF_PART);
            const int o0 = pl * 128;
            const int r0 = lid >> 2;
            const int cb = 2 * (lid & 3);
#pragma unroll
            for (int mf = 0; mf < 2; mf++) {
                int R0 = wm * 32 + mf * 16 + r0;
                int R1 = R0 + 8;
                const float* lA = g_l + (size_t)((m0 + R0) / SEQ) * HDIM + o0;
                const float* lB = g_l + (size_t)((m0 + R1) / SEQ) * HDIM + o0;
                float p0 = 0.0f, p1 = 0.0f;
#pragma unroll
                for (int nf = 0; nf < 4; nf++) {
                    int cl = wn * 32 + nf * 8 + cb;
                    p0 += fast_tanh(acc[mf][nf][0] + lA[cl])     * svre[o0 + cl];
                    p0 += fast_tanh(acc[mf][nf][1] + lA[cl + 1]) * svre[o0 + cl + 1];
                    p1 += fast_tanh(acc[mf][nf][2] + lB[cl])     * svre[o0 + cl];
                    p1 += fast_tanh(acc[mf][nf][3] + lB[cl + 1]) * svre[o0 + cl + 1];
#pragma unroll
                    for (int q = 0; q < 4; q++) acc[mf][nf][q] = 0.0f;
                }
                p0 += __shfl_xor_sync(0xffffffffu, p0, 1);
                p0 += __shfl_xor_sync(0xffffffffu, p0, 2);
                p1 += __shfl_xor_sync(0xffffffffu, p1, 1);
                p1 += __shfl_xor_sync(0xffffffffu, p1, 2);
                if ((lid & 3) == 0) {
                    part[R0 * 4 + wn] = p0;
                    part[R1 * 4 + wn] = p1;
                }
            }
            __syncthreads();
            if (tid < 64) {
                float s = part[tid * 4 + 0] + part[tid * 4 + 1]
                        + part[tid * 4 + 2] + part[tid * 4 + 3];
                g_spart[pl][m0 + tid] = s;
            }
        }
    }
}

// =============================================================================
// K3: per-batch softmax over S, context (fp16 g_Ah), 2-class head (~80us)
// =============================================================================
__device__ __forceinline__ float block_reduce_max(float v, float* red, int tid) {
    red[tid] = v; __syncthreads();
#pragma unroll
    for (int off = 128; off > 0; off >>= 1) {
        if (tid < off) red[tid] = fmaxf(red[tid], red[tid + off]);
        __syncthreads();
    }
    float r = red[0]; __syncthreads(); return r;
}
__device__ __forceinline__ float block_reduce_sum(float v, float* red, int tid) {
    red[tid] = v; __syncthreads();
#pragma unroll
    for (int off = 128; off > 0; off >>= 1) {
        if (tid < off) red[tid] = red[tid] + red[tid + off];
        __syncthreads();
    }
    float r = red[0]; __syncthreads(); return r;
}

__global__ void __launch_bounds__(256)
finish_kernel(const float* __restrict__ wre,
              float* __restrict__ out)
{
    const int b = blockIdx.x, tid = threadIdx.x;
    __shared__ float attn[SEQ];
    __shared__ float red[256];

    float sc = -INFINITY;
    if (tid < SEQ) {
        float s = 0.0f;
#pragma unroll
        for (int p = 0; p < NPLANES; p++) s += g_spart[p][(size_t)b * SEQ + tid];
        sc = s;
    }
    float mx = block_reduce_max(sc, red, tid);
    float e = (tid < SEQ) ? expf(sc - mx) : 0.0f;
    float denom = block_reduce_sum(e, red, tid);
    if (tid < SEQ) attn[tid] = e / denom;
    __syncthreads();

    const __half* am = g_Ah + (size_t)b * SEQ * HDIM;
    float c0a = 0.0f, c1a = 0.0f, c0b = 0.0f, c1b = 0.0f;
#pragma unroll 2
    for (int s = 0; s < SEQ; s += 2) {
        float w0 = attn[s];
        float w1 = attn[s + 1];
        __half2 ha = *reinterpret_cast<const __half2*>(am + (size_t)s * HDIM + 2 * tid);
        __half2 hb = *reinterpret_cast<const __half2*>(am + (size_t)(s + 1) * HDIM + 2 * tid);
        float2 fa = __half22float2(ha);
        float2 fb = __half22float2(hb);
        c0a = fmaf(w0, fa.x, c0a);
        c1a = fmaf(w0, fa.y, c1a);
        c0b = fmaf(w1, fb.x, c0b);
        c1b = fmaf(w1, fb.y, c1b);
    }
    float c0 = c0a + c0b, c1 = c1a + c1b;
    float p0 = c0 * wre[2 * tid]        + c1 * wre[2 * tid + 1];
    float p1 = c0 * wre[HDIM + 2 * tid] + c1 * wre[HDIM + 2 * tid + 1];
    float L0 = block_reduce_sum(p0, red, tid);
    float L1 = block_reduce_sum(p1, red, tid);
    if (tid == 0) {
        float m  = fmaxf(L0, L1);
        float e0 = expf(L0 - m), e1 = expf(L1 - m);
        float inv = 1.0f / (e0 + e1);
        out[(size_t)b * 2 + 0] = e0 * inv;
        out[(size_t)b * 2 + 1] = e1 * inv;
    }
}

// =============================================================================
// launch
// =============================================================================
extern "C" void kernel_launch(void* const* d_in, const int* in_sizes, int n_in,
                              void* d_out, int out_size)
{
    const float* all_memory  = (const float*)d_in[0];
    const float* last_memory = (const float*)d_in[1];
    const float* Ur_w        = (const float*)d_in[2];
    const float* Wr_w        = (const float*)d_in[3];
    const float* Vre_w       = (const float*)d_in[4];
    const float* Wre_w       = (const float*)d_in[5];
    float* out = (float*)d_out;

    cudaFuncSetAttribute(score_kernel,
                         cudaFuncAttributeMaxDynamicSharedMemorySize, SMEM_TOTAL);

    whalf_kernel<<<256, 256>>>(Ur_w);
    gemm_l_kernel<<<dim3(BATCH / 64, HDIM / 128), 256>>>(last_memory, Wr_w);
    score_kernel<<<MTOT / 64, 256, SMEM_TOTAL>>>(all_memory, Vre_w);
    finish_kernel<<<BATCH, 256>>>(Wre_w, out);
}

// round 12
// speedup vs baseline: 1.1488x; 1.0221x over previous
#include <cuda_runtime.h>
#include <cuda_fp16.h>
#include <math.h>
#include <cstdint>

#define BATCH 2048
#define SEQ   200
#define HDIM  512
#define MTOT  (BATCH * SEQ)   // 409600
#define NPLANES 4             // 4 o-tiles of 128 cols

// ---------------- static device scratch (no allocation) ----------------
__device__ float  g_l[BATCH * HDIM];          // Wr(last_memory)  [B,512]
__device__ float  g_spart[NPLANES][MTOT];     // partial scores
__device__ __half g_Wh[HDIM * HDIM];          // Ur_w fp16
__device__ __half g_Ah[(size_t)MTOT * HDIM];  // all_memory fp16 (written by score)

// ======================= helpers =======================
__device__ __forceinline__ uint32_t smem_u32(const void* p) {
    uint32_t a;
    asm("{ .reg .u64 t; cvta.to.shared.u64 t, %1; cvt.u32.u64 %0, t; }"
        : "=r"(a) : "l"(p));
    return a;
}
// 64-byte-row swizzle (Swizzle<2,4,3>): conflict-free ldmatrix on 64B rows
#define SWZ64(off) ((off) ^ (((off) >> 3) & 0x30))

#define LDSM_X4(r, a) \
    asm volatile("ldmatrix.sync.aligned.m8n8.x4.shared.b16 {%0,%1,%2,%3}, [%4];" \
        : "=r"((r)[0]), "=r"((r)[1]), "=r"((r)[2]), "=r"((r)[3]) : "r"(a))
#define LDSM_X2(r, a) \
    asm volatile("ldmatrix.sync.aligned.m8n8.x2.shared.b16 {%0,%1}, [%2];" \
        : "=r"((r)[0]), "=r"((r)[1]) : "r"(a))
#define MMA_F16(d, a, b) \
    asm volatile("mma.sync.aligned.m16n8k16.row.col.f32.f16.f16.f32 " \
        "{%0,%1,%2,%3},{%4,%5,%6,%7},{%8,%9},{%0,%1,%2,%3};" \
        : "+f"((d)[0]), "+f"((d)[1]), "+f"((d)[2]), "+f"((d)[3]) \
        : "r"((a)[0]), "r"((a)[1]), "r"((a)[2]), "r"((a)[3]), \
          "r"((b)[0]), "r"((b)[1]))
#define CPASYNC16(dst, src) \
    asm volatile("cp.async.cg.shared.global [%0], [%1], 16;" \
        :: "r"(dst), "l"(src) : "memory")
#define CPASYNC_COMMIT() asm volatile("cp.async.commit_group;" ::: "memory")
#define CPASYNC_WAITG(n) asm volatile("cp.async.wait_group %0;" :: "n"(n) : "memory")
#define STS128(addr, a, b, c, d) \
    asm volatile("st.shared.v4.b32 [%0], {%1, %2, %3, %4};" \
        :: "r"(addr), "r"(a), "r"(b), "r"(c), "r"(d) : "memory")

__device__ __forceinline__ float fast_tanh(float x) {
    float e = __expf(2.0f * x);
    return 1.0f - __fdividef(2.0f, e + 1.0f);
}

// =============================================================================
// W convert kernel: Ur_w fp32 -> fp16 (tiny, ~5us)
// =============================================================================
__global__ void __launch_bounds__(256)
whalf_kernel(const float* __restrict__ Ur)
{
    int i = blockIdx.x * 256 + threadIdx.x;       // float4 units, 65536
    float4 v = reinterpret_cast<const float4*>(Ur)[i];
    __half2 h0 = __float22half2_rn(make_float2(v.x, v.y));
    __half2 h1 = __float22half2_rn(make_float2(v.z, v.w));
    reinterpret_cast<__half2*>(g_Wh)[2 * i + 0] = h0;
    reinterpret_cast<__half2*>(g_Wh)[2 * i + 1] = h1;
}

// =============================================================================
// K1: l = last_memory @ Wr^T  (SIMT fp32, ~52us)
// =============================================================================
__global__ void __launch_bounds__(256)
gemm_l_kernel(const float* __restrict__ A, const float* __restrict__ W)
{
    const int tid = threadIdx.x;
    const int tx  = tid & 15;
    const int ty  = tid >> 4;
    const int m0  = blockIdx.x * 64;
    const int o0  = blockIdx.y * 128;

    __shared__ float As[64][33];
    __shared__ float Ws[128][33];

    float acc[4][8];
#pragma unroll
    for (int i = 0; i < 4; i++)
#pragma unroll
        for (int j = 0; j < 8; j++) acc[i][j] = 0.0f;

    for (int k0 = 0; k0 < HDIM; k0 += 32) {
#pragma unroll
        for (int t = 0; t < 2; t++) {
            int f = t * 256 + tid, r = f >> 3, c4 = (f & 7) << 2;
            float4 v = *reinterpret_cast<const float4*>(&A[(size_t)(m0 + r) * HDIM + k0 + c4]);
            As[r][c4] = v.x; As[r][c4 + 1] = v.y; As[r][c4 + 2] = v.z; As[r][c4 + 3] = v.w;
        }
#pragma unroll
        for (int t = 0; t < 4; t++) {
            int f = t * 256 + tid, r = f >> 3, c4 = (f & 7) << 2;
            float4 v = *reinterpret_cast<const float4*>(&W[(size_t)(o0 + r) * HDIM + k0 + c4]);
            Ws[r][c4] = v.x; Ws[r][c4 + 1] = v.y; Ws[r][c4 + 2] = v.z; Ws[r][c4 + 3] = v.w;
        }
        __syncthreads();
#pragma unroll
        for (int kk = 0; kk < 32; kk++) {
            float a[4], w[8];
#pragma unroll
            for (int i = 0; i < 4; i++) a[i] = As[ty * 4 + i][kk];
#pragma unroll
            for (int j = 0; j < 8; j++) w[j] = Ws[tx + 16 * j][kk];
#pragma unroll
            for (int i = 0; i < 4; i++)
#pragma unroll
                for (int j = 0; j < 8; j++) acc[i][j] += a[i] * w[j];
        }
        __syncthreads();
    }
#pragma unroll
    for (int i = 0; i < 4; i++) {
        int m = m0 + ty * 4 + i;
#pragma unroll
        for (int j = 0; j < 8; j++)
            g_l[(size_t)m * HDIM + o0 + tx + 16 * j] = acc[i][j];
    }
}

// =============================================================================
// K2: fused convert + fp16 HMMA over ALL 4 o-planes, 64 m-rows per CTA.
// 32 iterations x K=64: two B half-chunks per iteration, 5-stage 8KB B ring.
// Fills issue AFTER the MMAs (stage of chunk 2t+5 is vacated by chunk 2t this
// iteration); WAITG(1) + one sync per iteration. smem 110.6KB -> 2 CTAs/SM.
// =============================================================================
#define OFF_VRE   0                       // 512 floats
#define OFF_PART  2048                    // 64*4 floats
#define OFF_A     4096
#define A_HC      4096                    // 64 rows x 32k fp16
#define OFF_B     (OFF_A + 16 * A_HC)     // 69632
#define B_STG     8192                    // 128 rows x 32k fp16
#define SMEM_TOTAL (OFF_B + 5 * B_STG)    // 110592

__global__ void __launch_bounds__(256, 2)
score_kernel(const float* __restrict__ A,       // all_memory fp32 [M,512]
             const float* __restrict__ vre)     // [512]
{
    extern __shared__ char smem[];
    const uint32_t sb  = smem_u32(smem);
    const int tid = threadIdx.x;
    const int wid = tid >> 5;
    const int lid = tid & 31;
    const int wm  = wid >> 2;     // 0..1
    const int wn  = wid & 3;      // 0..3
    const int m0  = blockIdx.x * 64;

    float* svre = reinterpret_cast<float*>(smem + OFF_VRE);
    svre[tid] = vre[tid];
    svre[tid + 256] = vre[tid + 256];

    // A producer: thread -> (row ar, 8-float quarter aq)
    const int ar = tid >> 2;                  // 0..63
    const int aq = tid & 3;                   // 0..3
    const float* Abase = A    + (size_t)(m0 + ar) * HDIM + aq * 8;
    __half*      AhOut = g_Ah + (size_t)(m0 + ar) * HDIM + aq * 8;
    const uint32_t aoff = (uint32_t)(ar * 64 + aq * 16);

    // B producer: thread -> (row br, 16-half half bh); 2 x cp.async 16B / chunk
    const int br = tid >> 1;                  // 0..127
    const int bh = tid & 1;
    const uint32_t boff = (uint32_t)(br * 64 + bh * 32);

    float acc[2][4][4];
#pragma unroll
    for (int i = 0; i < 2; i++)
#pragma unroll
        for (int j = 0; j < 4; j++)
#pragma unroll
            for (int q = 0; q < 4; q++) acc[i][j][q] = 0.0f;

    // ---- prologue: B chunks 0..3 (two commits); A hk 0,1 convert; va for 2,3
#pragma unroll
    for (int g = 0; g < 2; g++) {
#pragma unroll
        for (int d = 0; d < 2; d++) {
            const int bi = 2 * g + d;          // 0..3 (plane 0)
            const __half* src = g_Wh + (size_t)br * HDIM + bi * 32 + bh * 16;
            const uint32_t st = sb + OFF_B + (bi % 5) * B_STG;
            CPASYNC16(st + SWZ64(boff),      src);
            CPASYNC16(st + SWZ64(boff + 16), src + 8);
        }
        CPASYNC_COMMIT();
    }
    float4 va0, va1, va2, va3;
#pragma unroll
    for (int hk = 0; hk < 2; hk++) {
        float4 u = *reinterpret_cast<const float4*>(Abase + hk * 32);
        float4 v = *reinterpret_cast<const float4*>(Abase + hk * 32 + 4);
        __half2 h0 = __float22half2_rn(make_float2(u.x, u.y));
        __half2 h1 = __float22half2_rn(make_float2(u.z, u.w));
        __half2 h2 = __float22half2_rn(make_float2(v.x, v.y));
        __half2 h3 = __float22half2_rn(make_float2(v.z, v.w));
        STS128(sb + OFF_A + hk * A_HC + SWZ64(aoff),
               reinterpret_cast<uint32_t&>(h0), reinterpret_cast<uint32_t&>(h1),
               reinterpret_cast<uint32_t&>(h2), reinterpret_cast<uint32_t&>(h3));
        uint4 o;
        o.x = reinterpret_cast<uint32_t&>(h0); o.y = reinterpret_cast<uint32_t&>(h1);
        o.z = reinterpret_cast<uint32_t&>(h2); o.w = reinterpret_cast<uint32_t&>(h3);
        *reinterpret_cast<uint4*>(AhOut + hk * 32) = o;
    }
    va0 = *reinterpret_cast<const float4*>(Abase + 64);
    va1 = *reinterpret_cast<const float4*>(Abase + 68);
    va2 = *reinterpret_cast<const float4*>(Abase + 96);
    va3 = *reinterpret_cast<const float4*>(Abase + 100);

#pragma unroll 1
    for (int t = 0; t < 32; ++t) {
        const int pl = t >> 3;                 // plane 0..3
        const int hk0 = (2 * t) & 15;          // A half-chunk for first K=32

        if (t < 31) { CPASYNC_WAITG(1); } else { CPASYNC_WAITG(0); }
        __syncthreads();

        // plane 0: convert A hk 2t+2, 2t+3 (used next iter); prefetch 2t+4,2t+5
        if (pl == 0 && t < 7) {
            {
                __half2 h0 = __float22half2_rn(make_float2(va0.x, va0.y));
                __half2 h1 = __float22half2_rn(make_float2(va0.z, va0.w));
                __half2 h2 = __float22half2_rn(make_float2(va1.x, va1.y));
                __half2 h3 = __float22half2_rn(make_float2(va1.z, va1.w));
                STS128(sb + OFF_A + (2 * t + 2) * A_HC + SWZ64(aoff),
                       reinterpret_cast<uint32_t&>(h0), reinterpret_cast<uint32_t&>(h1),
                       reinterpret_cast<uint32_t&>(h2), reinterpret_cast<uint32_t&>(h3));
                uint4 o;
                o.x = reinterpret_cast<uint32_t&>(h0); o.y = reinterpret_cast<uint32_t&>(h1);
                o.z = reinterpret_cast<uint32_t&>(h2); o.w = reinterpret_cast<uint32_t&>(h3);
                *reinterpret_cast<uint4*>(AhOut + (2 * t + 2) * 32) = o;
            }
            {
                __half2 h0 = __float22half2_rn(make_float2(va2.x, va2.y));
                __half2 h1 = __float22half2_rn(make_float2(va2.z, va2.w));
                __half2 h2 = __float22half2_rn(make_float2(va3.x, va3.y));
                __half2 h3 = __float22half2_rn(make_float2(va3.z, va3.w));
                STS128(sb + OFF_A + (2 * t + 3) * A_HC + SWZ64(aoff),
                       reinterpret_cast<uint32_t&>(h0), reinterpret_cast<uint32_t&>(h1),
                       reinterpret_cast<uint32_t&>(h2), reinterpret_cast<uint32_t&>(h3));
                uint4 o;
                o.x = reinterpret_cast<uint32_t&>(h0); o.y = reinterpret_cast<uint32_t&>(h1);
                o.z = reinterpret_cast<uint32_t&>(h2); o.w = reinterpret_cast<uint32_t&>(h3);
                *reinterpret_cast<uint4*>(AhOut + (2 * t + 3) * 32) = o;
            }
            if (t < 6) {
                va0 = *reinterpret_cast<const float4*>(Abase + (2 * t + 4) * 32);
                va1 = *reinterpret_cast<const float4*>(Abase + (2 * t + 4) * 32 + 4);
                va2 = *reinterpret_cast<const float4*>(Abase + (2 * t + 5) * 32);
                va3 = *reinterpret_cast<const float4*>(Abase + (2 * t + 5) * 32 + 4);
            }
        }

        // ---- MMAs: two half-chunks (K=64 total) ----
#pragma unroll
        for (int d = 0; d < 2; d++) {
            const int hc = 2 * t + d;
            const uint32_t stA = sb + OFF_A + ((hc & 15)) * A_HC;
            const uint32_t stB = sb + OFF_B + (hc % 5) * B_STG;
#pragma unroll
            for (int ks = 0; ks < 2; ks++) {
                uint32_t bf[4][2];
#pragma unroll
                for (int nf = 0; nf < 4; nf++) {
                    uint32_t row = wn * 32 + nf * 8 + (lid & 7);
                    uint32_t kb  = ks * 32 + ((lid >> 3) & 1) * 16;
                    LDSM_X2(bf[nf], stB + SWZ64(row * 64 + kb));
                }
#pragma unroll
                for (int mf = 0; mf < 2; mf++) {
                    uint32_t row = wm * 32 + mf * 16 + (lid & 15);
                    uint32_t kb  = ks * 32 + (lid >> 4) * 16;
                    uint32_t af[4];
                    LDSM_X4(af, stA + SWZ64(row * 64 + kb));
#pragma unroll
                    for (int nf = 0; nf < 4; nf++)
                        MMA_F16(acc[mf][nf], af, bf[nf]);
                }
            }
        }

        // ---- fill B chunks 2t+4, 2t+5 (after MMA: their stages just freed) ----
        if (t < 30) {
#pragma unroll
            for (int d = 0; d < 2; d++) {
                const int bi = 2 * t + 4 + d;
                const __half* src = g_Wh + (size_t)((bi >> 4) * 128 + br) * HDIM
                                  + (bi & 15) * 32 + bh * 16;
                const uint32_t stn = sb + OFF_B + (bi % 5) * B_STG;
                CPASYNC16(stn + SWZ64(boff),      src);
                CPASYNC16(stn + SWZ64(boff + 16), src + 8);
            }
            CPASYNC_COMMIT();
        }

        // ---- end of plane: fused epilogue, reset acc ----
        if ((t & 7) == 7) {
            float* part = reinterpret_cast<float*>(smem + OFF_PART);
            const int o0 = pl * 128;
            const int r0 = lid >> 2;
            const int cb = 2 * (lid & 3);
#pragma unroll
            for (int mf = 0; mf < 2; mf++) {
                int R0 = wm * 32 + mf * 16 + r0;
                int R1 = R0 + 8;
                const float* lA = g_l + (size_t)((m0 + R0) / SEQ) * HDIM + o0;
                const float* lB = g_l + (size_t)((m0 + R1) / SEQ) * HDIM + o0;
                float p0 = 0.0f, p1 = 0.0f;
#pragma unroll
                for (int nf = 0; nf < 4; nf++) {
                    int cl = wn * 32 + nf * 8 + cb;
                    p0 += fast_tanh(acc[mf][nf][0] + lA[cl])     * svre[o0 + cl];
                    p0 += fast_tanh(acc[mf][nf][1] + lA[cl + 1]) * svre[o0 + cl + 1];
                    p1 += fast_tanh(acc[mf][nf][2] + lB[cl])     * svre[o0 + cl];
                    p1 += fast_tanh(acc[mf][nf][3] + lB[cl + 1]) * svre[o0 + cl + 1];
#pragma unroll
                    for (int q = 0; q < 4; q++) acc[mf][nf][q] = 0.0f;
                }
                p0 += __shfl_xor_sync(0xffffffffu, p0, 1);
                p0 += __shfl_xor_sync(0xffffffffu, p0, 2);
                p1 += __shfl_xor_sync(0xffffffffu, p1, 1);
                p1 += __shfl_xor_sync(0xffffffffu, p1, 2);
                if ((lid & 3) == 0) {
                    part[R0 * 4 + wn] = p0;
                    part[R1 * 4 + wn] = p1;
                }
            }
            __syncthreads();
            if (tid < 64) {
                float s = part[tid * 4 + 0] + part[tid * 4 + 1]
                        + part[tid * 4 + 2] + part[tid * 4 + 3];
                g_spart[pl][m0 + tid] = s;
            }
        }
    }
}

// =============================================================================
// K3: per-batch softmax over S, context (fp16 g_Ah), 2-class head (~80us)
// =============================================================================
__device__ __forceinline__ float block_reduce_max(float v, float* red, int tid) {
    red[tid] = v; __syncthreads();
#pragma unroll
    for (int off = 128; off > 0; off >>= 1) {
        if (tid < off) red[tid] = fmaxf(red[tid], red[tid + off]);
        __syncthreads();
    }
    float r = red[0]; __syncthreads(); return r;
}
__device__ __forceinline__ float block_reduce_sum(float v, float* red, int tid) {
    red[tid] = v; __syncthreads();
#pragma unroll
    for (int off = 128; off > 0; off >>= 1) {
        if (tid < off) red[tid] = red[tid] + red[tid + off];
        __syncthreads();
    }
    float r = red[0]; __syncthreads(); return r;
}

__global__ void __launch_bounds__(256)
finish_kernel(const float* __restrict__ wre,
              float* __restrict__ out)
{
    const int b = blockIdx.x, tid = threadIdx.x;
    __shared__ float attn[SEQ];
    __shared__ float red[256];

    float sc = -INFINITY;
    if (tid < SEQ) {
        float s = 0.0f;
#pragma unroll
        for (int p = 0; p < NPLANES; p++) s += g_spart[p][(size_t)b * SEQ + tid];
        sc = s;
    }
    float mx = block_reduce_max(sc, red, tid);
    float e = (tid < SEQ) ? expf(sc - mx) : 0.0f;
    float denom = block_reduce_sum(e, red, tid);
    if (tid < SEQ) attn[tid] = e / denom;
    __syncthreads();

    const __half* am = g_Ah + (size_t)b * SEQ * HDIM;
    float c0a = 0.0f, c1a = 0.0f, c0b = 0.0f, c1b = 0.0f;
#pragma unroll 2
    for (int s = 0; s < SEQ; s += 2) {
        float w0 = attn[s];
        float w1 = attn[s + 1];
        __half2 ha = *reinterpret_cast<const __half2*>(am + (size_t)s * HDIM + 2 * tid);
        __half2 hb = *reinterpret_cast<const __half2*>(am + (size_t)(s + 1) * HDIM + 2 * tid);
        float2 fa = __half22float2(ha);
        float2 fb = __half22float2(hb);
        c0a = fmaf(w0, fa.x, c0a);
        c1a = fmaf(w0, fa.y, c1a);
        c0b = fmaf(w1, fb.x, c0b);
        c1b = fmaf(w1, fb.y, c1b);
    }
    float c0 = c0a + c0b, c1 = c1a + c1b;
    float p0 = c0 * wre[2 * tid]        + c1 * wre[2 * tid + 1];
    float p1 = c0 * wre[HDIM + 2 * tid] + c1 * wre[HDIM + 2 * tid + 1];
    float L0 = block_reduce_sum(p0, red, tid);
    float L1 = block_reduce_sum(p1, red, tid);
    if (tid == 0) {
        float m  = fmaxf(L0, L1);
        float e0 = expf(L0 - m), e1 = expf(L1 - m);
        float inv = 1.0f / (e0 + e1);
        out[(size_t)b * 2 + 0] = e0 * inv;
        out[(size_t)b * 2 + 1] = e1 * inv;
    }
}

// =============================================================================
// launch
// =============================================================================
extern "C" void kernel_launch(void* const* d_in, const int* in_sizes, int n_in,
                              void* d_out, int out_size)
{
    const float* all_memory  = (const float*)d_in[0];
    const float* last_memory = (const float*)d_in[1];
    const float* Ur_w        = (const float*)d_in[2];
    const float* Wr_w        = (const float*)d_in[3];
    const float* Vre_w       = (const float*)d_in[4];
    const float* Wre_w       = (const float*)d_in[5];
    float* out = (float*)d_out;

    cudaFuncSetAttribute(score_kernel,
                         cudaFuncAttributeMaxDynamicSharedMemorySize, SMEM_TOTAL);

    whalf_kernel<<<256, 256>>>(Ur_w);
    gemm_l_kernel<<<dim3(BATCH / 64, HDIM / 128), 256>>>(last_memory, Wr_w);
    score_kernel<<<MTOT / 64, 256, SMEM_TOTAL>>>(all_memory, Vre_w);
    finish_kernel<<<BATCH, 256>>>(Wre_w, out);
}